// round 6
// baseline (speedup 1.0000x reference)
#include <cuda_runtime.h>
#include <cuda_bf16.h>

// Problem constants
#define NTOK   2048
#define FD     64        // feature dim
#define KW     5         // kernel width
#define PW     2         // half window
#define NH     16        // heads per group
#define TILE_N 64
#define THREADS 256

// out[b,g,n,f,m] = sum_k kv[b,g,n+k-2,f] * w[b,n,g,m,k]
//  g <  16 : kv = key,   w = softmax([0,0,10,0,0])  (identical for all m)
//  g >= 16 : kv = value, w per-token from emb_weight[ids][5:10], 3 softmax variants

__global__ __launch_bounds__(THREADS) void twiker_kernel(
    const int*   __restrict__ ids,     // [4,2048]
    const float* __restrict__ keyp,    // [4,16,2048,64]
    const float* __restrict__ valp,    // [4,16,2048,64]
    const float* __restrict__ emb,     // [32000,10]
    float*       __restrict__ out)     // [4,32,2048,64,3]
{
    __shared__ float sm_kv[(TILE_N + 2 * PW) * FD];   // 68*64 = 17408 B
    __shared__ float sm_w[TILE_N * 16];               // 15 weights/token, pad 16

    const int tid = threadIdx.x;
    const int n0  = blockIdx.x * TILE_N;
    const int g   = blockIdx.y;                       // 0..31
    const int b   = blockIdx.z;

    const bool is_value = (g >= NH);
    const float* kv = is_value
        ? (valp + (size_t)(b * NH + (g - NH)) * NTOK * FD)
        : (keyp + (size_t)(b * NH + g)        * NTOK * FD);

    // ---- Stage kv tile (with +/-2 halo, zero-padded) into smem, float4 ----
    #pragma unroll
    for (int idx = tid; idx < (TILE_N + 2 * PW) * (FD / 4); idx += THREADS) {
        int r  = idx >> 4;            // FD/4 = 16 float4 per row
        int c  = idx & 15;
        int gn = n0 - PW + r;
        float4 v = make_float4(0.f, 0.f, 0.f, 0.f);
        if (gn >= 0 && gn < NTOK)
            v = *(const float4*)(kv + (size_t)gn * FD + c * 4);
        *(float4*)(sm_kv + r * FD + c * 4) = v;
    }

    // ---- Value-head blocks: per-token softmax weights into smem ----
    if (is_value && tid < TILE_N) {
        const int n  = n0 + tid;
        const int id = ids[b * NTOK + n];
        const float* e = emb + (size_t)id * 10 + 5;
        const float l0 = e[0], l1 = e[1], l2 = e[2], l3 = e[3], l4 = e[4];
        float* w = sm_w + tid * 16;
        // m=0: softmax(l0..l4)
        {
            float mx = fmaxf(fmaxf(fmaxf(l0, l1), fmaxf(l2, l3)), l4);
            float e0 = expf(l0 - mx), e1 = expf(l1 - mx), e2 = expf(l2 - mx);
            float e3 = expf(l3 - mx), e4 = expf(l4 - mx);
            float inv = 1.0f / (e0 + e1 + e2 + e3 + e4);
            w[0] = e0 * inv; w[1] = e1 * inv; w[2] = e2 * inv;
            w[3] = e3 * inv; w[4] = e4 * inv;
        }
        // m=1: softmax([0, l1, l2, l3, 0])   (masked taps are logit 0, NOT -inf)
        {
            float mx = fmaxf(0.f, fmaxf(fmaxf(l1, l2), l3));
            float ez = expf(-mx), e1 = expf(l1 - mx), e2 = expf(l2 - mx), e3 = expf(l3 - mx);
            float inv = 1.0f / (2.f * ez + e1 + e2 + e3);
            w[5] = ez * inv; w[6] = e1 * inv; w[7] = e2 * inv;
            w[8] = e3 * inv; w[9] = ez * inv;
        }
        // m=2: softmax([0, 0, l2, 0, 0])
        {
            float mx = fmaxf(0.f, l2);
            float ez = expf(-mx), e2 = expf(l2 - mx);
            float inv = 1.0f / (4.f * ez + e2);
            w[10] = ez * inv; w[11] = ez * inv; w[12] = e2 * inv;
            w[13] = ez * inv; w[14] = ez * inv;
        }
    }
    __syncthreads();

    // ---- Compute + store ----
    const int f4 = tid & 15;         // float4 index along F
    const int nb = tid >> 4;         // 0..15
    const size_t out_head = (size_t)(b * 2 * NH + g) * NTOK * (FD * 3);

    // Key-head constant weights: softmax([0,0,10,0,0]) (max-subtracted like jax)
    const float e10 = expf(-10.0f);
    const float winv = 1.0f / (1.0f + 4.0f * e10);
    const float wc = winv, wsd = e10 * winv;

    #pragma unroll
    for (int i = 0; i < TILE_N / 16; ++i) {
        const int nl = nb + i * 16;                         // local token
        const float* row = sm_kv + nl * FD + f4 * 4;        // tap k lives at +k*FD
        float4 a0 = make_float4(0.f, 0.f, 0.f, 0.f);
        float4 a1 = a0, a2 = a0;

        if (is_value) {
            const float* w = sm_w + nl * 16;
            #pragma unroll
            for (int k = 0; k < KW; ++k) {
                float4 v = *(const float4*)(row + k * FD);
                float w0 = w[k], w1 = w[5 + k], w2 = w[10 + k];
                a0.x = fmaf(v.x, w0, a0.x); a0.y = fmaf(v.y, w0, a0.y);
                a0.z = fmaf(v.z, w0, a0.z); a0.w = fmaf(v.w, w0, a0.w);
                a1.x = fmaf(v.x, w1, a1.x); a1.y = fmaf(v.y, w1, a1.y);
                a1.z = fmaf(v.z, w1, a1.z); a1.w = fmaf(v.w, w1, a1.w);
                a2.x = fmaf(v.x, w2, a2.x); a2.y = fmaf(v.y, w2, a2.y);
                a2.z = fmaf(v.z, w2, a2.z); a2.w = fmaf(v.w, w2, a2.w);
            }
        } else {
            #pragma unroll
            for (int k = 0; k < KW; ++k) {
                float4 v = *(const float4*)(row + k * FD);
                float w0 = (k == PW) ? wc : wsd;
                a0.x = fmaf(v.x, w0, a0.x); a0.y = fmaf(v.y, w0, a0.y);
                a0.z = fmaf(v.z, w0, a0.z); a0.w = fmaf(v.w, w0, a0.w);
            }
            a1 = a0; a2 = a0;   // weights identical across boundary variants
        }

        // out[..., n, f, m]: thread covers f = 4*f4..4*f4+3, i.e. 12 contiguous
        // floats starting at f4*12 (16B aligned) -> 3 aligned float4 stores.
        float* op = out + out_head + (size_t)(n0 + nl) * (FD * 3) + f4 * 12;
        float4 s0 = make_float4(a0.x, a1.x, a2.x, a0.y);
        float4 s1 = make_float4(a1.y, a2.y, a0.z, a1.z);
        float4 s2 = make_float4(a2.z, a0.w, a1.w, a2.w);
        ((float4*)op)[0] = s0;
        ((float4*)op)[1] = s1;
        ((float4*)op)[2] = s2;
    }
}

extern "C" void kernel_launch(void* const* d_in, const int* in_sizes, int n_in,
                              void* d_out, int out_size) {
    const int*   ids  = (const int*)d_in[0];
    const float* keyp = (const float*)d_in[1];
    const float* valp = (const float*)d_in[2];
    const float* emb  = (const float*)d_in[3];
    float* out = (float*)d_out;

    dim3 grid(NTOK / TILE_N, 2 * NH, 4);   // (32, 32, 4)
    twiker_kernel<<<grid, THREADS>>>(ids, keyp, valp, emb, out);
}

// round 15
// speedup vs baseline: 1.5754x; 1.5754x over previous
#include <cuda_runtime.h>
#include <cuda_bf16.h>

#define NTOK   2048
#define FD     64
#define KW     5
#define PW     2
#define NH     16
#define TILE_N 64
#define THREADS 256

// out[b,g,n,f,m] = sum_k kv[b,g,n+k-2,f] * w[b,n,g,m,k]
//  g <  16 : kv = key,   w = softmax([0,0,10,0,0])  (same for all m) — no smem needed
//  g >= 16 : kv = value, 3 per-token softmax variants from emb_weight[ids][5:10]
//
// Thread mapping: f4 = tid&15 (float4 along F), q = tid>>4 (token quad).
// Each thread covers 4 CONSECUTIVE tokens -> 8 overlapping kv rows via direct
// predicated LDG.128 (halo rows shared with neighbor quad hit L1). No kv smem.

__global__ __launch_bounds__(THREADS) void twiker_kernel(
    const int*   __restrict__ ids,     // [4,2048]
    const float* __restrict__ keyp,    // [4,16,2048,64]
    const float* __restrict__ valp,    // [4,16,2048,64]
    const float* __restrict__ emb,     // [32000,10]
    float*       __restrict__ out)     // [4,32,2048,64,3]
{
    __shared__ float sm_w[TILE_N * 16];               // 15 weights/token, pad 16

    const int tid = threadIdx.x;
    const int n0  = blockIdx.x * TILE_N;
    const int g   = blockIdx.y;
    const int b   = blockIdx.z;

    const bool is_value = (g >= NH);
    const float* kv = is_value
        ? (valp + (size_t)(b * NH + (g - NH)) * NTOK * FD)
        : (keyp + (size_t)(b * NH + g)        * NTOK * FD);

    if (is_value) {
        if (tid < TILE_N) {
            const int n  = n0 + tid;
            const int id = ids[b * NTOK + n];
            const float* e = emb + (size_t)id * 10 + 5;
            const float l0 = e[0], l1 = e[1], l2 = e[2], l3 = e[3], l4 = e[4];
            float* w = sm_w + tid * 16;
            // m=0: softmax(l0..l4)
            {
                float mx = fmaxf(fmaxf(fmaxf(l0, l1), fmaxf(l2, l3)), l4);
                float e0 = expf(l0 - mx), e1 = expf(l1 - mx), e2 = expf(l2 - mx);
                float e3 = expf(l3 - mx), e4 = expf(l4 - mx);
                float inv = 1.0f / (e0 + e1 + e2 + e3 + e4);
                w[0] = e0 * inv; w[1] = e1 * inv; w[2] = e2 * inv;
                w[3] = e3 * inv; w[4] = e4 * inv;
            }
            // m=1: softmax([0,l1,l2,l3,0])  (masked taps are logit 0, not -inf)
            {
                float mx = fmaxf(0.f, fmaxf(fmaxf(l1, l2), l3));
                float ez = expf(-mx), e1 = expf(l1 - mx), e2 = expf(l2 - mx), e3 = expf(l3 - mx);
                float inv = 1.0f / (2.f * ez + e1 + e2 + e3);
                w[5] = ez * inv; w[6] = e1 * inv; w[7] = e2 * inv;
                w[8] = e3 * inv; w[9] = ez * inv;
            }
            // m=2: softmax([0,0,l2,0,0])
            {
                float mx = fmaxf(0.f, l2);
                float ez = expf(-mx), e2 = expf(l2 - mx);
                float inv = 1.0f / (4.f * ez + e2);
                w[10] = ez * inv; w[11] = ez * inv; w[12] = e2 * inv;
                w[13] = ez * inv; w[14] = ez * inv;
            }
        }
        __syncthreads();   // block-uniform branch: legal
    }

    const int f4 = tid & 15;
    const int q  = tid >> 4;            // token quad 0..15
    const int t0 = n0 + q * 4 - PW;     // first kv row needed

    // ---- 8 predicated direct loads cover taps for 4 consecutive tokens ----
    const float* col = kv + f4 * 4;
    float4 r[8];
    #pragma unroll
    for (int j = 0; j < 8; ++j) {
        int t = t0 + j;
        float4 v = make_float4(0.f, 0.f, 0.f, 0.f);
        if (t >= 0 && t < NTOK)
            v = __ldg((const float4*)(col + (size_t)t * FD));
        r[j] = v;
    }

    float* op0 = out + (size_t)(b * 2 * NH + g) * NTOK * (FD * 3)
                     + (size_t)(n0 + q * 4) * (FD * 3) + f4 * 12;

    if (is_value) {
        #pragma unroll
        for (int j = 0; j < 4; ++j) {
            const float4* wp = (const float4*)(sm_w + (q * 4 + j) * 16);
            float4 wa = wp[0], wb = wp[1], wc4 = wp[2], wd = wp[3];
            const float w0k[5] = { wa.x, wa.y, wa.z, wa.w, wb.x };
            const float w1k[5] = { wb.y, wb.z, wb.w, wc4.x, wc4.y };
            const float w2k[5] = { wc4.z, wc4.w, wd.x, wd.y, wd.z };

            float4 a0 = make_float4(0.f, 0.f, 0.f, 0.f), a1 = a0, a2 = a0;
            #pragma unroll
            for (int k = 0; k < KW; ++k) {
                float4 v = r[j + k];
                float u0 = w0k[k], u1 = w1k[k], u2 = w2k[k];
                a0.x = fmaf(v.x, u0, a0.x); a0.y = fmaf(v.y, u0, a0.y);
                a0.z = fmaf(v.z, u0, a0.z); a0.w = fmaf(v.w, u0, a0.w);
                a1.x = fmaf(v.x, u1, a1.x); a1.y = fmaf(v.y, u1, a1.y);
                a1.z = fmaf(v.z, u1, a1.z); a1.w = fmaf(v.w, u1, a1.w);
                a2.x = fmaf(v.x, u2, a2.x); a2.y = fmaf(v.y, u2, a2.y);
                a2.z = fmaf(v.z, u2, a2.z); a2.w = fmaf(v.w, u2, a2.w);
            }
            float4* op = (float4*)(op0 + (size_t)j * (FD * 3));
            __stcs(op + 0, make_float4(a0.x, a1.x, a2.x, a0.y));
            __stcs(op + 1, make_float4(a1.y, a2.y, a0.z, a1.z));
            __stcs(op + 2, make_float4(a2.z, a0.w, a1.w, a2.w));
        }
    } else {
        // key heads: constant softmax([0,0,10,0,0]); identical across m
        const float e10  = expf(-10.0f);
        const float winv = 1.0f / (1.0f + 4.0f * e10);
        const float wc = winv, wsd = e10 * winv;
        #pragma unroll
        for (int j = 0; j < 4; ++j) {
            float4 a = make_float4(0.f, 0.f, 0.f, 0.f);
            #pragma unroll
            for (int k = 0; k < KW; ++k) {
                float4 v = r[j + k];
                float u = (k == PW) ? wc : wsd;
                a.x = fmaf(v.x, u, a.x); a.y = fmaf(v.y, u, a.y);
                a.z = fmaf(v.z, u, a.z); a.w = fmaf(v.w, u, a.w);
            }
            float4* op = (float4*)(op0 + (size_t)j * (FD * 3));
            __stcs(op + 0, make_float4(a.x, a.x, a.x, a.y));
            __stcs(op + 1, make_float4(a.y, a.y, a.z, a.z));
            __stcs(op + 2, make_float4(a.z, a.w, a.w, a.w));
        }
    }
}

extern "C" void kernel_launch(void* const* d_in, const int* in_sizes, int n_in,
                              void* d_out, int out_size) {
    const int*   ids  = (const int*)d_in[0];
    const float* keyp = (const float*)d_in[1];
    const float* valp = (const float*)d_in[2];
    const float* emb  = (const float*)d_in[3];
    float* out = (float*)d_out;

    dim3 grid(NTOK / TILE_N, 2 * NH, 4);   // (32, 32, 4)
    twiker_kernel<<<grid, THREADS>>>(ids, keyp, valp, emb, out);
}

// round 17
// speedup vs baseline: 1.9099x; 1.2124x over previous
#include <cuda_runtime.h>
#include <cuda_bf16.h>

#define NTOK   2048
#define FD     64
#define KW     5
#define PW     2
#define NH     16
#define TILE_N 64
#define THREADS 256
#define ROWPAD 204   // 192 floats per token + 12 pad (51 float4)

// out[b,g,n,f,m] = sum_k kv[b,g,n+k-2,f] * w[b,n,g,m,k]
// Loads: 8 predicated LDG.128/thread (4 consecutive tokens + halo, L1 reuse).
// Stores: per-j smem transpose -> fully coalesced STG.128 (kills the 3x
// wavefront amplification of the 48B-stride interleaved pattern).

__global__ __launch_bounds__(THREADS) void twiker_kernel(
    const int*   __restrict__ ids,     // [4,2048]
    const float* __restrict__ keyp,    // [4,16,2048,64]
    const float* __restrict__ valp,    // [4,16,2048,64]
    const float* __restrict__ emb,     // [32000,10]
    float*       __restrict__ out)     // [4,32,2048,64,3]
{
    __shared__ float sm_w[TILE_N * 16];   // 15 weights/token, pad 16 (4 KB)
    __shared__ float sm_t[16 * ROWPAD];   // transpose buffer: 16 tokens/j (12.75 KB)

    const int tid = threadIdx.x;
    const int n0  = blockIdx.x * TILE_N;
    const int g   = blockIdx.y;
    const int b   = blockIdx.z;

    const bool is_value = (g >= NH);
    const float* kv = is_value
        ? (valp + (size_t)(b * NH + (g - NH)) * NTOK * FD)
        : (keyp + (size_t)(b * NH + g)        * NTOK * FD);

    if (is_value) {
        if (tid < TILE_N) {
            const int n  = n0 + tid;
            const int id = ids[b * NTOK + n];
            const float* e = emb + (size_t)id * 10 + 5;
            const float l0 = e[0], l1 = e[1], l2 = e[2], l3 = e[3], l4 = e[4];
            float* w = sm_w + tid * 16;
            // m=0: softmax(l0..l4)
            {
                float mx = fmaxf(fmaxf(fmaxf(l0, l1), fmaxf(l2, l3)), l4);
                float e0 = expf(l0 - mx), e1 = expf(l1 - mx), e2 = expf(l2 - mx);
                float e3 = expf(l3 - mx), e4 = expf(l4 - mx);
                float inv = 1.0f / (e0 + e1 + e2 + e3 + e4);
                w[0] = e0 * inv; w[1] = e1 * inv; w[2] = e2 * inv;
                w[3] = e3 * inv; w[4] = e4 * inv;
            }
            // m=1: softmax([0,l1,l2,l3,0])  (masked taps are logit 0, not -inf)
            {
                float mx = fmaxf(0.f, fmaxf(fmaxf(l1, l2), l3));
                float ez = expf(-mx), e1 = expf(l1 - mx), e2 = expf(l2 - mx), e3 = expf(l3 - mx);
                float inv = 1.0f / (2.f * ez + e1 + e2 + e3);
                w[5] = ez * inv; w[6] = e1 * inv; w[7] = e2 * inv;
                w[8] = e3 * inv; w[9] = ez * inv;
            }
            // m=2: softmax([0,0,l2,0,0])
            {
                float mx = fmaxf(0.f, l2);
                float ez = expf(-mx), e2 = expf(l2 - mx);
                float inv = 1.0f / (4.f * ez + e2);
                w[10] = ez * inv; w[11] = ez * inv; w[12] = e2 * inv;
                w[13] = ez * inv; w[14] = ez * inv;
            }
        }
        __syncthreads();   // block-uniform branch: legal
    }

    const int f4 = tid & 15;
    const int q  = tid >> 4;            // token quad 0..15
    const int t0 = n0 + q * 4 - PW;

    // ---- 8 predicated direct loads cover taps for 4 consecutive tokens ----
    const float* col = kv + f4 * 4;
    float4 r[8];
    #pragma unroll
    for (int j = 0; j < 8; ++j) {
        int t = t0 + j;
        float4 v = make_float4(0.f, 0.f, 0.f, 0.f);
        if (t >= 0 && t < NTOK)
            v = __ldg((const float4*)(col + (size_t)t * FD));
        r[j] = v;
    }

    // key-head constant weights: softmax([0,0,10,0,0])
    const float e10  = expf(-10.0f);
    const float kinv = 1.0f / (1.0f + 4.0f * e10);
    const float wc = kinv, wsd = e10 * kinv;

    const size_t head4 = (size_t)(b * 2 * NH + g) * NTOK * 48;   // float4 units
    float4* sm_t4 = (float4*)sm_t;

    #pragma unroll
    for (int j = 0; j < 4; ++j) {
        float4 a0 = make_float4(0.f, 0.f, 0.f, 0.f), a1 = a0, a2 = a0;

        if (is_value) {
            const float4* wp = (const float4*)(sm_w + (q * 4 + j) * 16);
            float4 wa = wp[0], wb = wp[1], wcv = wp[2], wd = wp[3];
            const float w0k[5] = { wa.x, wa.y, wa.z, wa.w, wb.x };
            const float w1k[5] = { wb.y, wb.z, wb.w, wcv.x, wcv.y };
            const float w2k[5] = { wcv.z, wcv.w, wd.x, wd.y, wd.z };
            #pragma unroll
            for (int k = 0; k < KW; ++k) {
                float4 v = r[j + k];
                float u0 = w0k[k], u1 = w1k[k], u2 = w2k[k];
                a0.x = fmaf(v.x, u0, a0.x); a0.y = fmaf(v.y, u0, a0.y);
                a0.z = fmaf(v.z, u0, a0.z); a0.w = fmaf(v.w, u0, a0.w);
                a1.x = fmaf(v.x, u1, a1.x); a1.y = fmaf(v.y, u1, a1.y);
                a1.z = fmaf(v.z, u1, a1.z); a1.w = fmaf(v.w, u1, a1.w);
                a2.x = fmaf(v.x, u2, a2.x); a2.y = fmaf(v.y, u2, a2.y);
                a2.z = fmaf(v.z, u2, a2.z); a2.w = fmaf(v.w, u2, a2.w);
            }
        } else {
            #pragma unroll
            for (int k = 0; k < KW; ++k) {
                float4 v = r[j + k];
                float u = (k == PW) ? wc : wsd;
                a0.x = fmaf(v.x, u, a0.x); a0.y = fmaf(v.y, u, a0.y);
                a0.z = fmaf(v.z, u, a0.z); a0.w = fmaf(v.w, u, a0.w);
            }
            a1 = a0; a2 = a0;   // weights identical across boundary variants
        }

        // ---- STS interleaved [f][m] layout into token-row q ----
        // floats at q*ROWPAD + f4*12 + {0,4,8}; 48B lane stride, conflict-free
        float* tw = sm_t + q * ROWPAD + f4 * 12;
        *(float4*)(tw + 0) = make_float4(a0.x, a1.x, a2.x, a0.y);
        *(float4*)(tw + 4) = make_float4(a1.y, a2.y, a0.z, a1.z);
        *(float4*)(tw + 8) = make_float4(a2.z, a0.w, a1.w, a2.w);

        __syncthreads();

        // ---- read back linearly, coalesced streaming stores ----
        // 16 tokens * 48 float4 = 768 chunks; warp covers 32 consecutive.
        #pragma unroll
        for (int i = 0; i < 3; ++i) {
            int c  = i * THREADS + tid;
            int tr = c / 48;            // token row 0..15
            int ic = c % 48;            // intra-token float4 index
            float4 v = sm_t4[tr * (ROWPAD / 4) + ic];
            size_t o = head4 + (size_t)(n0 + tr * 4 + j) * 48 + ic;
            __stcs((float4*)out + o, v);
        }

        __syncthreads();   // buffer reuse guard for next j
    }
}

extern "C" void kernel_launch(void* const* d_in, const int* in_sizes, int n_in,
                              void* d_out, int out_size) {
    const int*   ids  = (const int*)d_in[0];
    const float* keyp = (const float*)d_in[1];
    const float* valp = (const float*)d_in[2];
    const float* emb  = (const float*)d_in[3];
    float* out = (float*)d_out;

    dim3 grid(NTOK / TILE_N, 2 * NH, 4);   // (32, 32, 4)
    twiker_kernel<<<grid, THREADS>>>(ids, keyp, valp, emb, out);
}